// round 2
// baseline (speedup 1.0000x reference)
#include <cuda_runtime.h>
#include <cuda_bf16.h>
#include <cstdint>

// BlockLinear: y[b, n*256+o] = sum_i x[b, n*256+i] * w[n,o,i] + bias[n*256+o]
// B=4096, N_BLOCKS=64, IN=OUT=256.  fp32 in/out, tf32 tensor-core math.

#define BM 128
#define BN 128
#define BK 32
#define KST (BK + 4)   // smem row stride (floats); (4g+t)%32 -> conflict-free frag loads

__device__ __forceinline__ uint32_t f2tf32(float a) {
    uint32_t u;
    asm("cvt.rna.tf32.f32 %0, %1;" : "=r"(u) : "f"(a));
    return u;
}

__device__ __forceinline__ void mma_tf32(float* c, const uint32_t* a, uint32_t b0, uint32_t b1) {
    asm volatile(
        "mma.sync.aligned.m16n8k8.row.col.f32.tf32.tf32.f32 "
        "{%0,%1,%2,%3}, {%4,%5,%6,%7}, {%8,%9}, {%0,%1,%2,%3};"
        : "+f"(c[0]), "+f"(c[1]), "+f"(c[2]), "+f"(c[3])
        : "r"(a[0]), "r"(a[1]), "r"(a[2]), "r"(a[3]), "r"(b0), "r"(b1));
}

__global__ __launch_bounds__(256, 2)
void block_linear_kernel(const float* __restrict__ X,
                         const float* __restrict__ W,
                         const float* __restrict__ Bias,
                         float* __restrict__ Y)
{
    __shared__ float As[BM * KST];
    __shared__ float Bs[BN * KST];

    const int nb = blockIdx.z;          // diag block 0..63
    const int m0 = blockIdx.y * BM;     // batch-row tile
    const int n0 = blockIdx.x * BN;     // out-col tile within 256

    const int tid  = threadIdx.x;
    const int warp = tid >> 5;
    const int lane = tid & 31;
    const int wm   = warp & 3;          // 4 warps along M (each 32 rows)
    const int wn   = warp >> 2;         // 2 warps along N (each 64 cols)
    const int g    = lane >> 2;         // group 0..7
    const int tg   = lane & 3;          // thread-in-group 0..3

    // gmem tile load mapping: each thread loads 4 rows x float4, 32 rows/pass
    const int lrow = tid >> 3;          // 0..31
    const int lcol = (tid & 7) << 2;    // 0,4,...,28

    const float* xg = X + (size_t)(m0 + lrow) * 16384 + (size_t)nb * 256 + lcol;
    const float* wg = W + (size_t)nb * 65536 + (size_t)(n0 + lrow) * 256 + lcol;

    float acc[2][8][4];
    #pragma unroll
    for (int mt = 0; mt < 2; ++mt)
        #pragma unroll
        for (int nt = 0; nt < 8; ++nt)
            #pragma unroll
            for (int i = 0; i < 4; ++i) acc[mt][nt][i] = 0.0f;

    // prefetch A chunk 0 into registers (hide DRAM latency)
    float4 pa[4];
    #pragma unroll
    for (int i = 0; i < 4; ++i)
        pa[i] = *reinterpret_cast<const float4*>(xg + (size_t)i * 32 * 16384);

    #pragma unroll 1
    for (int kc = 0; kc < 8; ++kc) {
        const int k0 = kc * BK;

        // Store A (prefetched) and B (L2-resident weights) to SMEM with tf32 rounding.
        #pragma unroll
        for (int i = 0; i < 4; ++i) {
            float4 b = *reinterpret_cast<const float4*>(wg + (size_t)i * 32 * 256 + k0);
            float* db = &Bs[(lrow + i * 32) * KST + lcol];
            db[0] = __uint_as_float(f2tf32(b.x));
            db[1] = __uint_as_float(f2tf32(b.y));
            db[2] = __uint_as_float(f2tf32(b.z));
            db[3] = __uint_as_float(f2tf32(b.w));

            float4 a = pa[i];
            float* da = &As[(lrow + i * 32) * KST + lcol];
            da[0] = __uint_as_float(f2tf32(a.x));
            da[1] = __uint_as_float(f2tf32(a.y));
            da[2] = __uint_as_float(f2tf32(a.z));
            da[3] = __uint_as_float(f2tf32(a.w));
        }
        __syncthreads();

        // Issue next A chunk loads; they complete while we compute.
        if (kc < 7) {
            #pragma unroll
            for (int i = 0; i < 4; ++i)
                pa[i] = *reinterpret_cast<const float4*>(
                    xg + (size_t)i * 32 * 16384 + (k0 + BK));
        }

        // Compute: 4 k-steps of 8, 2 M-tiles x 8 N-tiles of m16n8k8 per warp.
        #pragma unroll
        for (int ks = 0; ks < 4; ++ks) {
            const int kk = ks * 8;

            uint32_t afr[2][4];
            #pragma unroll
            for (int mt = 0; mt < 2; ++mt) {
                const int ar = wm * 32 + mt * 16 + g;
                afr[mt][0] = __float_as_uint(As[ar        * KST + kk + tg]);
                afr[mt][1] = __float_as_uint(As[(ar + 8)  * KST + kk + tg]);
                afr[mt][2] = __float_as_uint(As[ar        * KST + kk + tg + 4]);
                afr[mt][3] = __float_as_uint(As[(ar + 8)  * KST + kk + tg + 4]);
            }

            #pragma unroll
            for (int nt = 0; nt < 8; ++nt) {
                const int br = wn * 64 + nt * 8 + g;
                const uint32_t b0 = __float_as_uint(Bs[br * KST + kk + tg]);
                const uint32_t b1 = __float_as_uint(Bs[br * KST + kk + tg + 4]);
                mma_tf32(acc[0][nt], afr[0], b0, b1);
                mma_tf32(acc[1][nt], afr[1], b0, b1);
            }
        }
        __syncthreads();
    }

    // Epilogue: bias add, fp32 store. C frag: c0/c1 at (g, 2t/2t+1), c2/c3 at (g+8, ...).
    #pragma unroll
    for (int mt = 0; mt < 2; ++mt) {
        const int row0 = m0 + wm * 32 + mt * 16 + g;
        #pragma unroll
        for (int nt = 0; nt < 8; ++nt) {
            const int gcol = nb * 256 + n0 + wn * 64 + nt * 8 + tg * 2;
            const float b0 = Bias[gcol];
            const float b1 = Bias[gcol + 1];
            float2 v0 = make_float2(acc[mt][nt][0] + b0, acc[mt][nt][1] + b1);
            float2 v1 = make_float2(acc[mt][nt][2] + b0, acc[mt][nt][3] + b1);
            *reinterpret_cast<float2*>(Y + (size_t)row0       * 16384 + gcol) = v0;
            *reinterpret_cast<float2*>(Y + (size_t)(row0 + 8) * 16384 + gcol) = v1;
        }
    }
}

extern "C" void kernel_launch(void* const* d_in, const int* in_sizes, int n_in,
                              void* d_out, int out_size) {
    const float* x    = (const float*)d_in[0];
    const float* w    = (const float*)d_in[1];
    const float* bias = (const float*)d_in[2];
    float* y          = (float*)d_out;

    dim3 grid(256 / BN, 4096 / BM, 64);   // (2, 32, 64)
    block_linear_kernel<<<grid, 256>>>(x, w, bias, y);
}

// round 4
// speedup vs baseline: 1.2138x; 1.2138x over previous
#include <cuda_runtime.h>
#include <cuda_fp16.h>
#include <cstdint>

// BlockLinear: y[b, nb*256+o] = sum_i x[b, nb*256+i]*w[nb,o,i] + bias
// fp32 in/out; fp16 HMMA m16n8k16 math (same 10-bit mantissa as tf32).
// CTA tile 128x128, BK=32, double-buffered smem, ldmatrix fragments.

#define THREADS 256
#define ROWB 80                 // smem row stride bytes (5*16B): (5r+c)%8 distinct -> ldmatrix conflict-free
#define ASTG (128 * ROWB)       // 10240 B per A (or B) tile
#define STG  (2 * ASTG)         // 20480 B per stage (A + B)

__device__ __forceinline__ uint32_t pk2(float a, float b) {
    __half2 h = __floats2half2_rn(a, b);
    return *reinterpret_cast<uint32_t*>(&h);
}

__device__ __forceinline__ void ldm4(uint32_t* r, uint32_t addr) {
    asm volatile("ldmatrix.sync.aligned.m8n8.x4.shared.b16 {%0,%1,%2,%3}, [%4];"
                 : "=r"(r[0]), "=r"(r[1]), "=r"(r[2]), "=r"(r[3]) : "r"(addr));
}

__device__ __forceinline__ void mma16816(float* c, const uint32_t* a, const uint32_t* b) {
    asm volatile(
        "mma.sync.aligned.m16n8k16.row.col.f32.f16.f16.f32 "
        "{%0,%1,%2,%3},{%4,%5,%6,%7},{%8,%9},{%0,%1,%2,%3};"
        : "+f"(c[0]), "+f"(c[1]), "+f"(c[2]), "+f"(c[3])
        : "r"(a[0]), "r"(a[1]), "r"(a[2]), "r"(a[3]), "r"(b[0]), "r"(b[1]));
}

__global__ __launch_bounds__(THREADS, 2)
void block_linear_f16(const float* __restrict__ X, const float* __restrict__ W,
                      const float* __restrict__ Bias, float* __restrict__ Y)
{
    __shared__ __align__(16) unsigned char smT[2 * STG];   // 40960 B
    __shared__ float smBias[128];

    const int nb = blockIdx.z;
    const int m0 = blockIdx.y << 7;
    const int n0 = blockIdx.x << 7;

    const int tid  = threadIdx.x;
    const int warp = tid >> 5;
    const int lane = tid & 31;
    const int wm   = warp & 3;          // 4 warps along M (32 rows each)
    const int wn   = warp >> 2;         // 2 warps along N (64 cols each)
    const int g    = lane >> 2;
    const int tg   = lane & 3;

    if (tid < 128) smBias[tid] = Bias[nb * 256 + n0 + tid];

    // ---- tile-fill mapping: thread -> 2 rows x one 8-float k-segment ----
    const int frow = tid >> 2;          // 0..63 (second slot +64)
    const int fc   = tid & 3;           // k-segment 0..3 (8 floats each)
    const float* xg = X + (size_t)(m0 + frow) * 16384 + nb * 256 + fc * 8;
    const float* wg = W + (size_t)nb * 65536 + (size_t)(n0 + frow) * 256 + fc * 8;
    unsigned char* sA0 = smT;
    unsigned char* sB0 = smT + ASTG;
    const uint32_t aoff = frow * ROWB + fc * 16;

    // ---- ldmatrix lane addressing ----
    const uint32_t smT_u = (uint32_t)__cvta_generic_to_shared(smT);
    const int la = lane & 15, ha = lane >> 4;                 // A: rows 0-15 / k-half
    const uint32_t aAddr = smT_u + (wm * 32 + la) * ROWB + ha * 16;
    const int lb = (lane & 7) + ((lane >> 4) << 3);           // B: n row within pair
    const int cb = (lane >> 3) & 1;                           // B: k-half
    const uint32_t bAddr = smT_u + ASTG + (wn * 64 + lb) * ROWB + cb * 16;

    float acc[2][8][4];
    #pragma unroll
    for (int mt = 0; mt < 2; ++mt)
        #pragma unroll
        for (int nt = 0; nt < 8; ++nt)
            #pragma unroll
            for (int i = 0; i < 4; ++i) acc[mt][nt][i] = 0.0f;

    // ---- prologue: fill chunk 0 into stage 0 ----
    #pragma unroll
    for (int i = 0; i < 2; ++i) {
        float4 a0 = *(const float4*)(xg + (size_t)i * 64 * 16384);
        float4 a1 = *(const float4*)(xg + (size_t)i * 64 * 16384 + 4);
        uint4 va = {pk2(a0.x, a0.y), pk2(a0.z, a0.w), pk2(a1.x, a1.y), pk2(a1.z, a1.w)};
        *(uint4*)(sA0 + i * 64 * ROWB + aoff) = va;
        float4 b0 = *(const float4*)(wg + (size_t)i * 64 * 256);
        float4 b1 = *(const float4*)(wg + (size_t)i * 64 * 256 + 4);
        uint4 vb = {pk2(b0.x, b0.y), pk2(b0.z, b0.w), pk2(b1.x, b1.y), pk2(b1.z, b1.w)};
        *(uint4*)(sB0 + i * 64 * ROWB + aoff) = vb;
    }
    __syncthreads();

    #pragma unroll 1
    for (int kc = 0; kc < 8; ++kc) {
        const int st = kc & 1;

        // prefetch next A chunk (X streams from DRAM) into regs; B waits (L2-hot)
        float4 pa[4];
        if (kc < 7) {
            const int kb = (kc + 1) * 32;
            #pragma unroll
            for (int i = 0; i < 2; ++i) {
                pa[2 * i]     = *(const float4*)(xg + (size_t)i * 64 * 16384 + kb);
                pa[2 * i + 1] = *(const float4*)(xg + (size_t)i * 64 * 16384 + kb + 4);
            }
        }

        // ---- compute stage st: 2 k16-steps ----
        const uint32_t aB = aAddr + st * STG;
        const uint32_t bB = bAddr + st * STG;
        #pragma unroll
        for (int ks = 0; ks < 2; ++ks) {
            uint32_t aF[2][4], bF[8][2];
            ldm4(aF[0], aB + ks * 32);
            ldm4(aF[1], aB + 16 * ROWB + ks * 32);
            #pragma unroll
            for (int p = 0; p < 4; ++p) {
                uint32_t t[4];
                ldm4(t, bB + p * 16 * ROWB + ks * 32);
                bF[2 * p][0]     = t[0]; bF[2 * p][1]     = t[1];
                bF[2 * p + 1][0] = t[2]; bF[2 * p + 1][1] = t[3];
            }
            #pragma unroll
            for (int nt = 0; nt < 8; ++nt) {
                mma16816(acc[0][nt], aF[0], bF[nt]);
                mma16816(acc[1][nt], aF[1], bF[nt]);
            }
        }

        // ---- fill next stage ----
        if (kc < 7) {
            const int kb  = (kc + 1) * 32;
            const int stn = st ^ 1;
            #pragma unroll
            for (int i = 0; i < 2; ++i) {
                float4 b0 = *(const float4*)(wg + (size_t)i * 64 * 256 + kb);
                float4 b1 = *(const float4*)(wg + (size_t)i * 64 * 256 + kb + 4);
                uint4 vb = {pk2(b0.x, b0.y), pk2(b0.z, b0.w), pk2(b1.x, b1.y), pk2(b1.z, b1.w)};
                *(uint4*)(sB0 + stn * STG + i * 64 * ROWB + aoff) = vb;
                uint4 va = {pk2(pa[2 * i].x, pa[2 * i].y), pk2(pa[2 * i].z, pa[2 * i].w),
                            pk2(pa[2 * i + 1].x, pa[2 * i + 1].y), pk2(pa[2 * i + 1].z, pa[2 * i + 1].w)};
                *(uint4*)(sA0 + stn * STG + i * 64 * ROWB + aoff) = va;
            }
            __syncthreads();
        }
    }

    // ---- epilogue: bias + fp32 stores ----
    #pragma unroll
    for (int mt = 0; mt < 2; ++mt) {
        const int row0 = m0 + wm * 32 + mt * 16 + g;
        #pragma unroll
        for (int nt = 0; nt < 8; ++nt) {
            const int lcol = wn * 64 + nt * 8 + tg * 2;     // 0..127
            const int gcol = nb * 256 + n0 + lcol;
            const float b0 = smBias[lcol];
            const float b1 = smBias[lcol + 1];
            float2 v0 = make_float2(acc[mt][nt][0] + b0, acc[mt][nt][1] + b1);
            float2 v1 = make_float2(acc[mt][nt][2] + b0, acc[mt][nt][3] + b1);
            *reinterpret_cast<float2*>(Y + (size_t)row0       * 16384 + gcol) = v0;
            *reinterpret_cast<float2*>(Y + (size_t)(row0 + 8) * 16384 + gcol) = v1;
        }
    }
}

extern "C" void kernel_launch(void* const* d_in, const int* in_sizes, int n_in,
                              void* d_out, int out_size) {
    const float* x    = (const float*)d_in[0];
    const float* w    = (const float*)d_in[1];
    const float* bias = (const float*)d_in[2];
    float* y          = (float*)d_out;

    dim3 grid(2, 32, 64);   // (n-tile, m-slab, diag block)
    block_linear_f16<<<grid, THREADS>>>(x, w, bias, y);
}